// round 13
// baseline (speedup 1.0000x reference)
#include <cuda_runtime.h>

#define NCLS   20
#define IMGSZ  600.0f
#define BATCH  16
#define NA     65536
#define NM     32
#define TPB    256
#define APB    512                  // anchors per block (2 per thread)
#define BLKPI  (NA / APB)           // 128 blocks per image
#define NBLK   (BATCH * BLKPI)      // 2048 blocks
#define L2E    1.4426950408889634f
#define LN2    0.6931471805599453f

__device__ float        g_part[3 * NBLK];
__device__ unsigned int g_count = 0;

__device__ __forceinline__ float ex2f(float x) {
    float y; asm("ex2.approx.ftz.f32 %0, %1;" : "=f"(y) : "f"(x)); return y;
}
__device__ __forceinline__ float lg2f(float x) {
    float y; asm("lg2.approx.ftz.f32 %0, %1;" : "=f"(y) : "f"(x)); return y;
}

// acc += sigmoid(x)^2 * log2(1+e^x)   (true focal neg term = 0.75*ln2 * this)
__device__ __forceinline__ void negterm_add(float x, float& acc) {
    float t = x * L2E;
    float e = ex2f(t);
    float l = lg2f(1.0f + e);
    float d = t - l;
    float q = ex2f(d + d);
    acc = fmaf(q, l, acc);
}

__device__ __forceinline__ float smooth_l1(float d) {
    float ad = fabsf(d);
    return (ad < 1.0f) ? 0.5f * d * d : ad - 0.5f;
}

__global__ void __launch_bounds__(TPB, 5) k_main(
    const float* __restrict__ loc_preds,   // [B, A, 4]
    const float* __restrict__ cls_preds,   // [B, A, 20]
    const float* __restrict__ iou_boxes,   // [A, 4] xywh
    const float* __restrict__ targets,     // [B*M, 6]
    float* __restrict__ out)
{
    __shared__ float4 s_box[NM];    // (-x1, -y1, x2+1, y2+1)
    __shared__ float4 s_xywh[NM];   // cx, cy, w, h
    __shared__ float  s_ar[NM];     // (w+1)*(h+1)
    __shared__ int    s_lab[NM];
    __shared__ float  s_red[24];
    __shared__ int    s_last;

    const int tid  = threadIdx.x;
    const int lane = tid & 31;
    const int b    = blockIdx.x >> 7;                  // 128 blocks per image
    const int a0   = ((blockIdx.x & 127) << 9) + tid;  // anchor A
    const int a1   = a0 + 256;                         // anchor B
    const size_t idx0 = (size_t)b * NA + (size_t)a0;
    const size_t idx1 = idx0 + 256;
    const size_t warp_a0 = idx0 & ~(size_t)31;         // warp's first anchor (set A)

    if (tid < NM) {
        const float* tr = targets + ((b << 5) + tid) * 6;
        float cx = tr[2] * IMGSZ, cy = tr[3] * IMGSZ;
        float w  = tr[4] * IMGSZ, h  = tr[5] * IMGSZ;
        s_xywh[tid] = make_float4(cx, cy, w, h);
        s_box[tid]  = make_float4(0.5f * w - cx, 0.5f * h - cy,     // -x1, -y1
                                  cx + 0.5f * w + 1.0f, cy + 0.5f * h + 1.0f);
        s_ar[tid]  = (w + 1.0f) * (h + 1.0f);
        s_lab[tid] = (int)tr[1];
    }
    __syncthreads();

    // Anchor constants for IoU
    float nax1A, nay1A, ax2A, ay2A, aarA;
    float nax1B, nay1B, ax2B, ay2B, aarB;
    {
        float4 av0 = ((const float4*)iou_boxes)[a0];
        nax1A = 0.5f * av0.z - av0.x; nay1A = 0.5f * av0.w - av0.y;
        ax2A  = av0.x + 0.5f * av0.z + 1.0f; ay2A = av0.y + 0.5f * av0.w + 1.0f;
        aarA  = (av0.z + 1.0f) * (av0.w + 1.0f);
        float4 av1 = ((const float4*)iou_boxes)[a1];
        nax1B = 0.5f * av1.z - av1.x; nay1B = 0.5f * av1.w - av1.y;
        ax2B  = av1.x + 0.5f * av1.z + 1.0f; ay2B = av1.y + 0.5f * av1.w + 1.0f;
        aarB  = (av1.z + 1.0f) * (av1.w + 1.0f);
    }

    const float4* wpA = (const float4*)(cls_preds + warp_a0 * NCLS);
    const float4* wpB = (const float4*)(cls_preds + (warp_a0 + 256) * NCLS);

    // ---- FUSED loop: dense focal (MUFU-heavy) interleaved with IoU (ALU/FMA) ----
    // 8 steps; each step does 4 IoU targets; steps 0..4 also do one focal
    // float4-pair (8 negterms). One unrolled basic block -> ptxas hides MUFU
    // latency/throughput under IoU issue slots.
    float Aacc = 0.0f;
    float biA = 0.0f, bSA = 1.0f; int bmA = 0;
    float biB = 0.0f, bSB = 1.0f; int bmB = 0;
#pragma unroll
    for (int k = 0; k < 8; k++) {
        if (k < 5) {
            float4 qa = wpA[lane + 32 * k];
            float4 qb = wpB[lane + 32 * k];
            negterm_add(qa.x, Aacc); negterm_add(qa.y, Aacc);
            negterm_add(qa.z, Aacc); negterm_add(qa.w, Aacc);
            negterm_add(qb.x, Aacc); negterm_add(qb.y, Aacc);
            negterm_add(qb.z, Aacc); negterm_add(qb.w, Aacc);
        }
        float4 ar4 = ((const float4*)s_ar)[k];
        float ars[4] = {ar4.x, ar4.y, ar4.z, ar4.w};
#pragma unroll
        for (int mi = 0; mi < 4; mi++) {
            int m = k * 4 + mi;
            float4 tb = s_box[m];
            float wiA = fminf(ax2A, tb.z) + fminf(nax1A, tb.x);
            float hiA = fminf(ay2A, tb.w) + fminf(nay1A, tb.y);
            float inA = fmaxf(wiA, 0.0f) * fmaxf(hiA, 0.0f);
            float SA  = aarA + ars[mi];
            if (inA * bSA > biA * SA) { biA = inA; bSA = SA; bmA = m; }

            float wiB = fminf(ax2B, tb.z) + fminf(nax1B, tb.x);
            float hiB = fminf(ay2B, tb.w) + fminf(nay1B, tb.y);
            float inB = fmaxf(wiB, 0.0f) * fmaxf(hiB, 0.0f);
            float SB  = aarB + ars[mi];
            if (inB * bSB > biB * SB) { biB = inB; bSB = SB; bmB = m; }
        }
    }

    // iou >= 0.5  <=>  3*bi >= bS ;  iou > 0.4  <=>  7*bi > 2*bS
    bool posA = 3.0f * biA >= bSA;
    bool ignA = (!posA) && (7.0f * biA > 2.0f * bSA);
    bool posB = 3.0f * biB >= bSB;
    bool ignB = (!posB) && (7.0f * biB > 2.0f * bSB);

    // ---- Warp-cooperative ignored-anchor corrections (two 32-bit masks) ----
    float Corr = 0.0f;
    unsigned mAm = __ballot_sync(0xffffffffu, ignA);
    unsigned mBm = __ballot_sync(0xffffffffu, ignB);
    while (mAm) {
        int src = __ffs(mAm) - 1;
        mAm &= mAm - 1;
        const float* cp = cls_preds + (warp_a0 + (size_t)src) * NCLS;
        if (lane < NCLS) negterm_add(cp[lane], Corr);
    }
    while (mBm) {
        int src = __ffs(mBm) - 1;
        mBm &= mBm - 1;
        const float* cp = cls_preds + (warp_a0 + 256 + (size_t)src) * NCLS;
        if (lane < NCLS) negterm_add(cp[lane], Corr);
    }

    // ---- Positive anchors (rare): reload anchor box from gmem (L2-hot) ----
    float Cacc = 0.0f, Lacc = 0.0f, posf = 0.0f;
#pragma unroll
    for (int s = 0; s < 2; s++) {
        bool pos = s ? posB : posA;
        if (!pos) continue;
        int m = s ? bmB : bmA;
        size_t idx = s ? idx1 : idx0;
        float4 av = ((const float4*)iou_boxes)[s ? a1 : a0];
        float acx = av.x, acy = av.y, aw = av.z, ah = av.w;

        posf += 1.0f;
        int pc = s_lab[m];
        float x = cls_preds[idx * NCLS + pc];
        float t = x * L2E;
        float e = ex2f(t);
        float l = lg2f(1.0f + e);
        float d = t - l;
        float q = ex2f(d + d);          // sigmoid^2
        float p = ex2f(d);              // sigmoid
        float sp = LN2 * l;             // softplus(x)
        float omp = 1.0f - p;
        Cacc += 0.25f * omp * omp * (sp - x) - (0.75f * LN2) * (q * l);

        float4 tw = s_xywh[m];
        float4 lp = ((const float4*)loc_preds)[idx];
        float invw = __fdividef(1.0f, aw);
        float invh = __fdividef(1.0f, ah);
        float tx = (tw.x - acx) * invw;
        float ty = (tw.y - acy) * invh;
        float tww = __logf(tw.z * invw);
        float thh = __logf(tw.w * invh);
        Lacc += smooth_l1(lp.x - tx) + smooth_l1(lp.y - ty)
              + smooth_l1(lp.z - tww) + smooth_l1(lp.w - thh);
    }

    float cls_acc = fmaf(Aacc - Corr, 0.75f * LN2, Cacc);

    // ---- Block reduction ----
#pragma unroll
    for (int o = 16; o; o >>= 1) {
        Lacc    += __shfl_down_sync(0xffffffffu, Lacc, o);
        cls_acc += __shfl_down_sync(0xffffffffu, cls_acc, o);
        posf    += __shfl_down_sync(0xffffffffu, posf, o);
    }
    int wid = tid >> 5;
    if (lane == 0) {
        s_red[wid]      = Lacc;
        s_red[8 + wid]  = cls_acc;
        s_red[16 + wid] = posf;
    }
    __syncthreads();
    if (tid == 0) {
        float r0 = 0.f, r1 = 0.f, r2 = 0.f;
#pragma unroll
        for (int i = 0; i < 8; i++) { r0 += s_red[i]; r1 += s_red[8+i]; r2 += s_red[16+i]; }
        g_part[blockIdx.x]            = r0;
        g_part[NBLK + blockIdx.x]     = r1;
        g_part[2 * NBLK + blockIdx.x] = r2;
        __threadfence();
        unsigned int o = atomicAdd(&g_count, 1u);
        s_last = (o == (unsigned)(gridDim.x - 1));
    }
    __syncthreads();

    // ---- Last block finalizes ----
    if (s_last) {
        __threadfence();
        double l = 0.0, c = 0.0, p = 0.0;
        for (int i = tid; i < NBLK; i += TPB) {
            l += (double)g_part[i];
            c += (double)g_part[NBLK + i];
            p += (double)g_part[2 * NBLK + i];
        }
        __shared__ double d_red[3 * 8];
#pragma unroll
        for (int o = 16; o; o >>= 1) {
            l += __shfl_down_sync(0xffffffffu, l, o);
            c += __shfl_down_sync(0xffffffffu, c, o);
            p += __shfl_down_sync(0xffffffffu, p, o);
        }
        if (lane == 0) { d_red[wid] = l; d_red[8 + wid] = c; d_red[16 + wid] = p; }
        __syncthreads();
        if (tid == 0) {
            double L = 0.0, C = 0.0, P = 0.0;
#pragma unroll
            for (int i = 0; i < 8; i++) { L += d_red[i]; C += d_red[8+i]; P += d_red[16+i]; }
            if (P < 1.0) P = 1.0;
            out[0] = (float)((L + C) / P);
            out[1] = (float)(L / P);
            out[2] = (float)(C / P);
            g_count = 0;   // reset for next graph replay
        }
    }
}

extern "C" void kernel_launch(void* const* d_in, const int* in_sizes, int n_in,
                              void* d_out, int out_size) {
    const float* loc_preds = (const float*)d_in[0];
    const float* cls_preds = (const float*)d_in[1];
    const float* iou_boxes = (const float*)d_in[2];
    const float* targets   = (const float*)d_in[3];
    float* out = (float*)d_out;

    k_main<<<NBLK, TPB>>>(loc_preds, cls_preds, iou_boxes, targets, out);
}

// round 14
// speedup vs baseline: 1.5344x; 1.5344x over previous
#include <cuda_runtime.h>

#define NCLS   20
#define IMGSZ  600.0f
#define BATCH  16
#define NA     65536
#define NM     32
#define TPB    256
#define APB    512                  // anchors per block (2 per thread)
#define BLKPI  (NA / APB)           // 128 blocks per image
#define NBLK   (BATCH * BLKPI)      // 2048 blocks
#define L2E    1.4426950408889634f
#define LN2    0.6931471805599453f

__device__ float        g_part[3 * NBLK];
__device__ unsigned int g_count = 0;

__device__ __forceinline__ float ex2f(float x) {
    float y; asm("ex2.approx.ftz.f32 %0, %1;" : "=f"(y) : "f"(x)); return y;
}
__device__ __forceinline__ float lg2f(float x) {
    float y; asm("lg2.approx.ftz.f32 %0, %1;" : "=f"(y) : "f"(x)); return y;
}

// acc += sigmoid(x)^2 * log2(1+e^x)   (true focal neg term = 0.75*ln2 * this)
__device__ __forceinline__ void negterm_add(float x, float& acc) {
    float t = x * L2E;
    float e = ex2f(t);
    float l = lg2f(1.0f + e);
    float d = t - l;
    float q = ex2f(d + d);
    acc = fmaf(q, l, acc);
}

__device__ __forceinline__ float smooth_l1(float d) {
    float ad = fabsf(d);
    return (ad < 1.0f) ? 0.5f * d * d : ad - 0.5f;
}

__global__ void __launch_bounds__(TPB, 5) k_main(
    const float* __restrict__ loc_preds,   // [B, A, 4]
    const float* __restrict__ cls_preds,   // [B, A, 20]
    const float* __restrict__ iou_boxes,   // [A, 4] xywh
    const float* __restrict__ targets,     // [B*M, 6]
    float* __restrict__ out)
{
    __shared__ float4 s_box[NM];    // (-x1, -y1, x2+1, y2+1)
    __shared__ float4 s_xywh[NM];   // cx, cy, w, h
    __shared__ float  s_ar[NM];     // (w+1)*(h+1)
    __shared__ int    s_lab[NM];
    __shared__ float  s_red[24];
    __shared__ int    s_last;

    const int tid  = threadIdx.x;
    const int lane = tid & 31;
    const int b    = blockIdx.x >> 7;                  // 128 blocks per image
    const int a0   = ((blockIdx.x & 127) << 9) + tid;  // anchor A
    const int a1   = a0 + 256;                         // anchor B
    const size_t idx0 = (size_t)b * NA + (size_t)a0;
    const size_t idx1 = idx0 + 256;
    const size_t warp_a0 = idx0 & ~(size_t)31;         // warp's first anchor (set A)

    if (tid < NM) {
        const float* tr = targets + ((b << 5) + tid) * 6;
        float cx = tr[2] * IMGSZ, cy = tr[3] * IMGSZ;
        float w  = tr[4] * IMGSZ, h  = tr[5] * IMGSZ;
        s_xywh[tid] = make_float4(cx, cy, w, h);
        s_box[tid]  = make_float4(0.5f * w - cx, 0.5f * h - cy,     // -x1, -y1
                                  cx + 0.5f * w + 1.0f, cy + 0.5f * h + 1.0f);
        s_ar[tid]  = (w + 1.0f) * (h + 1.0f);
        s_lab[tid] = (int)tr[1];
    }
    __syncthreads();

    // Anchor constants for IoU
    float nax1A, nay1A, ax2A, ay2A, aarA;
    float nax1B, nay1B, ax2B, ay2B, aarB;
    {
        float4 av0 = ((const float4*)iou_boxes)[a0];
        nax1A = 0.5f * av0.z - av0.x; nay1A = 0.5f * av0.w - av0.y;
        ax2A  = av0.x + 0.5f * av0.z + 1.0f; ay2A = av0.y + 0.5f * av0.w + 1.0f;
        aarA  = (av0.z + 1.0f) * (av0.w + 1.0f);
        float4 av1 = ((const float4*)iou_boxes)[a1];
        nax1B = 0.5f * av1.z - av1.x; nay1B = 0.5f * av1.w - av1.y;
        ax2B  = av1.x + 0.5f * av1.z + 1.0f; ay2B = av1.y + 0.5f * av1.w + 1.0f;
        aarB  = (av1.z + 1.0f) * (av1.w + 1.0f);
    }

    const float4* wpA = (const float4*)(cls_preds + warp_a0 * NCLS);
    const float4* wpB = (const float4*)(cls_preds + (warp_a0 + 256) * NCLS);

    // ---- FUSED loop: dense focal (MUFU-heavy) interleaved with IoU (ALU/FMA) ----
    // 8 steps; each step does 4 IoU targets; steps 0..4 also do one focal
    // float4-pair (8 negterms). One unrolled basic block -> ptxas hides MUFU
    // latency/throughput under IoU issue slots.
    float Aacc = 0.0f;
    float biA = 0.0f, bSA = 1.0f; int bmA = 0;
    float biB = 0.0f, bSB = 1.0f; int bmB = 0;
#pragma unroll
    for (int k = 0; k < 8; k++) {
        if (k < 5) {
            float4 qa = wpA[lane + 32 * k];
            float4 qb = wpB[lane + 32 * k];
            negterm_add(qa.x, Aacc); negterm_add(qa.y, Aacc);
            negterm_add(qa.z, Aacc); negterm_add(qa.w, Aacc);
            negterm_add(qb.x, Aacc); negterm_add(qb.y, Aacc);
            negterm_add(qb.z, Aacc); negterm_add(qb.w, Aacc);
        }
        float4 ar4 = ((const float4*)s_ar)[k];
        float ars[4] = {ar4.x, ar4.y, ar4.z, ar4.w};
#pragma unroll
        for (int mi = 0; mi < 4; mi++) {
            int m = k * 4 + mi;
            float4 tb = s_box[m];
            float wiA = fminf(ax2A, tb.z) + fminf(nax1A, tb.x);
            float hiA = fminf(ay2A, tb.w) + fminf(nay1A, tb.y);
            float inA = fmaxf(wiA, 0.0f) * fmaxf(hiA, 0.0f);
            float SA  = aarA + ars[mi];
            if (inA * bSA > biA * SA) { biA = inA; bSA = SA; bmA = m; }

            float wiB = fminf(ax2B, tb.z) + fminf(nax1B, tb.x);
            float hiB = fminf(ay2B, tb.w) + fminf(nay1B, tb.y);
            float inB = fmaxf(wiB, 0.0f) * fmaxf(hiB, 0.0f);
            float SB  = aarB + ars[mi];
            if (inB * bSB > biB * SB) { biB = inB; bSB = SB; bmB = m; }
        }
    }

    // iou >= 0.5  <=>  3*bi >= bS ;  iou > 0.4  <=>  7*bi > 2*bS
    bool posA = 3.0f * biA >= bSA;
    bool ignA = (!posA) && (7.0f * biA > 2.0f * bSA);
    bool posB = 3.0f * biB >= bSB;
    bool ignB = (!posB) && (7.0f * biB > 2.0f * bSB);

    // ---- Warp-cooperative ignored-anchor corrections (two 32-bit masks) ----
    float Corr = 0.0f;
    unsigned mAm = __ballot_sync(0xffffffffu, ignA);
    unsigned mBm = __ballot_sync(0xffffffffu, ignB);
    while (mAm) {
        int src = __ffs(mAm) - 1;
        mAm &= mAm - 1;
        const float* cp = cls_preds + (warp_a0 + (size_t)src) * NCLS;
        if (lane < NCLS) negterm_add(cp[lane], Corr);
    }
    while (mBm) {
        int src = __ffs(mBm) - 1;
        mBm &= mBm - 1;
        const float* cp = cls_preds + (warp_a0 + 256 + (size_t)src) * NCLS;
        if (lane < NCLS) negterm_add(cp[lane], Corr);
    }

    // ---- Positive anchors (rare): reload anchor box from gmem (L2-hot) ----
    float Cacc = 0.0f, Lacc = 0.0f, posf = 0.0f;
#pragma unroll
    for (int s = 0; s < 2; s++) {
        bool pos = s ? posB : posA;
        if (!pos) continue;
        int m = s ? bmB : bmA;
        size_t idx = s ? idx1 : idx0;
        float4 av = ((const float4*)iou_boxes)[s ? a1 : a0];
        float acx = av.x, acy = av.y, aw = av.z, ah = av.w;

        posf += 1.0f;
        int pc = s_lab[m];
        float x = cls_preds[idx * NCLS + pc];
        float t = x * L2E;
        float e = ex2f(t);
        float l = lg2f(1.0f + e);
        float d = t - l;
        float q = ex2f(d + d);          // sigmoid^2
        float p = ex2f(d);              // sigmoid
        float sp = LN2 * l;             // softplus(x)
        float omp = 1.0f - p;
        Cacc += 0.25f * omp * omp * (sp - x) - (0.75f * LN2) * (q * l);

        float4 tw = s_xywh[m];
        float4 lp = ((const float4*)loc_preds)[idx];
        float invw = __fdividef(1.0f, aw);
        float invh = __fdividef(1.0f, ah);
        float tx = (tw.x - acx) * invw;
        float ty = (tw.y - acy) * invh;
        float tww = __logf(tw.z * invw);
        float thh = __logf(tw.w * invh);
        Lacc += smooth_l1(lp.x - tx) + smooth_l1(lp.y - ty)
              + smooth_l1(lp.z - tww) + smooth_l1(lp.w - thh);
    }

    float cls_acc = fmaf(Aacc - Corr, 0.75f * LN2, Cacc);

    // ---- Block reduction ----
#pragma unroll
    for (int o = 16; o; o >>= 1) {
        Lacc    += __shfl_down_sync(0xffffffffu, Lacc, o);
        cls_acc += __shfl_down_sync(0xffffffffu, cls_acc, o);
        posf    += __shfl_down_sync(0xffffffffu, posf, o);
    }
    int wid = tid >> 5;
    if (lane == 0) {
        s_red[wid]      = Lacc;
        s_red[8 + wid]  = cls_acc;
        s_red[16 + wid] = posf;
    }
    __syncthreads();
    if (tid == 0) {
        float r0 = 0.f, r1 = 0.f, r2 = 0.f;
#pragma unroll
        for (int i = 0; i < 8; i++) { r0 += s_red[i]; r1 += s_red[8+i]; r2 += s_red[16+i]; }
        g_part[blockIdx.x]            = r0;
        g_part[NBLK + blockIdx.x]     = r1;
        g_part[2 * NBLK + blockIdx.x] = r2;
        __threadfence();
        unsigned int o = atomicAdd(&g_count, 1u);
        s_last = (o == (unsigned)(gridDim.x - 1));
    }
    __syncthreads();

    // ---- Last block finalizes ----
    if (s_last) {
        __threadfence();
        double l = 0.0, c = 0.0, p = 0.0;
        for (int i = tid; i < NBLK; i += TPB) {
            l += (double)g_part[i];
            c += (double)g_part[NBLK + i];
            p += (double)g_part[2 * NBLK + i];
        }
        __shared__ double d_red[3 * 8];
#pragma unroll
        for (int o = 16; o; o >>= 1) {
            l += __shfl_down_sync(0xffffffffu, l, o);
            c += __shfl_down_sync(0xffffffffu, c, o);
            p += __shfl_down_sync(0xffffffffu, p, o);
        }
        if (lane == 0) { d_red[wid] = l; d_red[8 + wid] = c; d_red[16 + wid] = p; }
        __syncthreads();
        if (tid == 0) {
            double L = 0.0, C = 0.0, P = 0.0;
#pragma unroll
            for (int i = 0; i < 8; i++) { L += d_red[i]; C += d_red[8+i]; P += d_red[16+i]; }
            if (P < 1.0) P = 1.0;
            out[0] = (float)((L + C) / P);
            out[1] = (float)(L / P);
            out[2] = (float)(C / P);
            g_count = 0;   // reset for next graph replay
        }
    }
}

extern "C" void kernel_launch(void* const* d_in, const int* in_sizes, int n_in,
                              void* d_out, int out_size) {
    const float* loc_preds = (const float*)d_in[0];
    const float* cls_preds = (const float*)d_in[1];
    const float* iou_boxes = (const float*)d_in[2];
    const float* targets   = (const float*)d_in[3];
    float* out = (float*)d_out;

    k_main<<<NBLK, TPB>>>(loc_preds, cls_preds, iou_boxes, targets, out);
}